// round 7
// baseline (speedup 1.0000x reference)
#include <cuda_runtime.h>
#include <math.h>

#define N_ROWS 8192
#define DIM    128

#define NT 64            // rows per block
#define OT 64            // cols per block
#define KC 32            // i-chunk staged in smem
#define NCH (DIM / KC)   // 4 chunks
#define THREADS 512
#define NR 2             // rows per thread
#define OR 4             // cols per thread
#define NTP 65           // padded float2 row stride

// ---- packed weights (prep kernel output) ----
// gG   : g (clipped)
// gWyz : (ln2*Wr, ln2*Wi)   -> multiplies lg2(R) into (A,B) with one FFMA2
// gPQ  : (-pi*g*Wi, pi*g*Wr)-> sign (x<0) contribution to (A,B), one FFMA2
__device__ float  gG  [DIM * DIM];
__device__ float2 gWyz[DIM * DIM];
__device__ float2 gPQ [DIM * DIM];

__global__ void NPU_prep_kernel(const float* __restrict__ Wr,
                                const float* __restrict__ Wi,
                                const float* __restrict__ G) {
    int idx = blockIdx.x * blockDim.x + threadIdx.x;
    if (idx >= DIM * DIM) return;
    float g = fminf(fmaxf(G[idx], 0.0f), 1.0f);
    float wr = Wr[idx];
    float wi = Wi[idx];
    const float LN2 = 0.69314718055994530942f;
    const float PI  = 3.14159265358979323846f;
    gG[idx]   = g;
    gWyz[idx] = make_float2(LN2 * wr, LN2 * wi);
    gPQ[idx]  = make_float2(-PI * g * wi, PI * g * wr);
}

// ---- smem layout (~57KB -> 2 blocks/SM) ----
#define SM_G_BYTES   (KC * OT * 4)     //  8192
#define SM_WYZ_BYTES (KC * OT * 8)     // 16384
#define SM_PQ_BYTES  (KC * OT * 8)     // 16384
#define SM_ROW_BYTES (KC * NTP * 8)    // 16640
#define SM_WYZ_OFF   (SM_G_BYTES)
#define SM_PQ_OFF    (SM_WYZ_OFF + SM_WYZ_BYTES)
#define SM_ROW_OFF   (SM_PQ_OFF + SM_PQ_BYTES)
#define SMEM_TOTAL   (SM_ROW_OFF + SM_ROW_BYTES)   // 57600 B

#define FMA_F32X2(d, a, b) \
    asm("fma.rn.f32x2 %0, %1, %2, %0;" : "+l"(d) : "l"(a), "l"(b))

#define PACK_DUP(d, s) \
    asm("mov.b64 %0, {%1, %1};" : "=l"(d) : "r"(s))

__global__ __launch_bounds__(THREADS, 2)
void NPU_main_kernel(const float* __restrict__ x, float* __restrict__ out) {
    extern __shared__ char smem[];
    float*  sG   = (float*) smem;                          // [KC][OT]
    float2* sWyz = (float2*)(smem + SM_WYZ_OFF);           // [KC][OT]
    float2* sPQ  = (float2*)(smem + SM_PQ_OFF);            // [KC][OT]
    float2* sRow = (float2*)(smem + SM_ROW_OFF);           // [KC][NTP] (am1, negf)

    const int tid = threadIdx.x;
    const int n0  = blockIdx.x * NT;
    const int o0  = blockIdx.y * OT;
    const int to  = (tid & 15) * OR;   // col offset in tile (16 col-threads)
    const int tn  = (tid >> 4) * NR;   // row offset in tile (32 row-threads)

    unsigned long long AB[NR][OR];
    #pragma unroll
    for (int r = 0; r < NR; r++)
        #pragma unroll
        for (int j = 0; j < OR; j++) AB[r][j] = 0ULL;

    for (int c = 0; c < NCH; c++) {
        const int i0 = c * KC;
        __syncthreads();   // previous chunk fully consumed

        // ---- stage weights: one float4 of g per thread, two float4 each wyz/pq ----
        {
            int ir = tid >> 4;            // 0..31
            int o4 = (tid & 15) * 4;
            *(float4*)&sG[ir * OT + o4] =
                *(const float4*)&gG[(i0 + ir) * DIM + o0 + o4];
        }
        #pragma unroll
        for (int k = tid; k < KC * OT / 2; k += THREADS) {
            int ir = k >> 5;              // 0..31
            int o2 = (k & 31) * 2;
            *(float4*)&sWyz[ir * OT + o2] =
                *(const float4*)&gWyz[(i0 + ir) * DIM + o0 + o2];
            *(float4*)&sPQ[ir * OT + o2] =
                *(const float4*)&gPQ[(i0 + ir) * DIM + o0 + o2];
        }
        // ---- stage rows: am1 = |x|+eps-1, negf = (x<0) ; [i][n] layout ----
        {
            int k  = tid;                 // NT*KC/4 = 512 = THREADS exactly
            int n  = k >> 3;              // 0..63
            int i4 = (k & 7) * 4;
            float4 xv = *(const float4*)&x[(n0 + n) * DIM + i0 + i4];
            sRow[(i4 + 0) * NTP + n] =
                make_float2((fabsf(xv.x) + 1e-36f) - 1.0f, xv.x < 0.0f ? 1.0f : 0.0f);
            sRow[(i4 + 1) * NTP + n] =
                make_float2((fabsf(xv.y) + 1e-36f) - 1.0f, xv.y < 0.0f ? 1.0f : 0.0f);
            sRow[(i4 + 2) * NTP + n] =
                make_float2((fabsf(xv.z) + 1e-36f) - 1.0f, xv.z < 0.0f ? 1.0f : 0.0f);
            sRow[(i4 + 3) * NTP + n] =
                make_float2((fabsf(xv.w) + 1e-36f) - 1.0f, xv.w < 0.0f ? 1.0f : 0.0f);
        }
        __syncthreads();

        // ---- hot loop (R3 codegen: scalar lg2, FFMA2 accumulate) ----
        #pragma unroll 2
        for (int i = 0; i < KC; i++) {
            float4 gv = *(const float4*)&sG[i * OT + to];
            ulonglong2 w01 = *(const ulonglong2*)&sWyz[i * OT + to];
            ulonglong2 w23 = *(const ulonglong2*)&sWyz[i * OT + to + 2];
            ulonglong2 p01 = *(const ulonglong2*)&sPQ [i * OT + to];
            ulonglong2 p23 = *(const ulonglong2*)&sPQ [i * OT + to + 2];
            unsigned long long wj[OR] = {w01.x, w01.y, w23.x, w23.y};
            unsigned long long pj[OR] = {p01.x, p01.y, p23.x, p23.y};
            float gj[OR] = {gv.x, gv.y, gv.z, gv.w};

            float2 rv[NR];
            unsigned long long nfnf[NR];
            #pragma unroll
            for (int r = 0; r < NR; r++) {
                rv[r] = sRow[i * NTP + tn + r];
                PACK_DUP(nfnf[r], __float_as_uint(rv[r].y));
            }

            #pragma unroll
            for (int r = 0; r < NR; r++) {
                #pragma unroll
                for (int j = 0; j < OR; j++) {
                    float R = fmaf(rv[r].x, gj[j], 1.0f);  // a*g + (1-g)
                    float t = __log2f(R);                   // MUFU.LG2
                    unsigned long long tt;
                    PACK_DUP(tt, __float_as_uint(t));
                    FMA_F32X2(AB[r][j], tt, wj[j]);         // (A,B) += t*(wy,wz)
                    FMA_F32X2(AB[r][j], nfnf[r], pj[j]);    // (A,B) += nf*(Pa,Q)
                }
            }
        }
    }

    // ---- epilogue: out = exp(A) * cos(B) ----
    #pragma unroll
    for (int r = 0; r < NR; r++) {
        float4 v;
        float av[OR], bv[OR];
        #pragma unroll
        for (int j = 0; j < OR; j++) {
            av[j] = __uint_as_float((unsigned int)(AB[r][j] & 0xffffffffULL));
            bv[j] = __uint_as_float((unsigned int)(AB[r][j] >> 32));
        }
        v.x = expf(av[0]) * cosf(bv[0]);
        v.y = expf(av[1]) * cosf(bv[1]);
        v.z = expf(av[2]) * cosf(bv[2]);
        v.w = expf(av[3]) * cosf(bv[3]);
        *(float4*)&out[(n0 + tn + r) * DIM + o0 + to] = v;
    }
}

extern "C" void kernel_launch(void* const* d_in, const int* in_sizes, int n_in,
                              void* d_out, int out_size) {
    const float* x  = (const float*)d_in[0];
    const float* Wr = (const float*)d_in[1];
    const float* Wi = (const float*)d_in[2];
    const float* G  = (const float*)d_in[3];
    float* out = (float*)d_out;
    (void)in_sizes; (void)n_in; (void)out_size;

    NPU_prep_kernel<<<(DIM * DIM + 255) / 256, 256>>>(Wr, Wi, G);

    cudaFuncSetAttribute(NPU_main_kernel,
                         cudaFuncAttributeMaxDynamicSharedMemorySize, SMEM_TOTAL);
    dim3 grid(N_ROWS / NT, DIM / OT);
    NPU_main_kernel<<<grid, THREADS, SMEM_TOTAL>>>(x, out);
}

// round 8
// speedup vs baseline: 1.5912x; 1.5912x over previous
#include <cuda_runtime.h>
#include <math.h>
#include <stdint.h>

#define N_ROWS 8192
#define DIM    128

#define NT 128           // rows per block
#define OT 64            // cols per block
#define KC 32            // i-chunk staged in smem
#define NCH (DIM / KC)   // 4 chunks
#define THREADS 512
#define NR 4             // rows per thread
#define OR 4             // cols per thread

// ---- packed weights (prep kernel output) ----
__device__ float  gG  [DIM * DIM];
__device__ float2 gWyz[DIM * DIM];   // (ln2*Wr, ln2*Wi)
__device__ float2 gPQ [DIM * DIM];   // (-pi*g*Wi, pi*g*Wr)
// ---- transformed+transposed rows: [i][n] = (am1, negf) ----
__device__ float2 gRowT[DIM * N_ROWS];

__global__ void NPU_prep_kernel(const float* __restrict__ Wr,
                                const float* __restrict__ Wi,
                                const float* __restrict__ G) {
    int idx = blockIdx.x * blockDim.x + threadIdx.x;
    if (idx >= DIM * DIM) return;
    float g = fminf(fmaxf(G[idx], 0.0f), 1.0f);
    float wr = Wr[idx];
    float wi = Wi[idx];
    const float LN2 = 0.69314718055994530942f;
    const float PI  = 3.14159265358979323846f;
    gG[idx]   = g;
    gWyz[idx] = make_float2(LN2 * wr, LN2 * wi);
    gPQ[idx]  = make_float2(-PI * g * wi, PI * g * wr);
}

// 32x32 tiled transpose + transform: x[n][i] -> gRowT[i][n] = (|x|+eps-1, x<0)
__global__ void NPU_xform_kernel(const float* __restrict__ x) {
    __shared__ float2 tile[32][33];
    int n0 = blockIdx.x * 32;
    int i0 = blockIdx.y * 32;
    int tx = threadIdx.x & 31;
    int ty = threadIdx.x >> 5;           // 0..7
    #pragma unroll
    for (int k = 0; k < 32; k += 8) {
        float xv = x[(n0 + ty + k) * DIM + i0 + tx];
        tile[ty + k][tx] =
            make_float2((fabsf(xv) + 1e-36f) - 1.0f, xv < 0.0f ? 1.0f : 0.0f);
    }
    __syncthreads();
    #pragma unroll
    for (int k = 0; k < 32; k += 8)
        gRowT[(i0 + ty + k) * N_ROWS + n0 + tx] = tile[tx][ty + k];
}

// ---- smem: two stages, each g + wyz + pq + rows ----
#define SG_OFF    0
#define SWYZ_OFF  (KC * OT * 4)                    //  8192
#define SPQ_OFF   (SWYZ_OFF + KC * OT * 8)         // 24576
#define SROW_OFF  (SPQ_OFF + KC * OT * 8)          // 40960
#define STG_BYTES (SROW_OFF + KC * NT * 8)         // 73728
#define SMEM_TOTAL (2 * STG_BYTES)                 // 147456

#define FMA_F32X2(d, a, b) \
    asm("fma.rn.f32x2 %0, %1, %2, %0;" : "+l"(d) : "l"(a), "l"(b))
#define PACK_DUP(d, s) \
    asm("mov.b64 %0, {%1, %1};" : "=l"(d) : "r"(s))

__device__ __forceinline__ void cp16(uint32_t dst, const void* src) {
    asm volatile("cp.async.cg.shared.global [%0], [%1], 16;"
                 :: "r"(dst), "l"(src));
}

__device__ __forceinline__ void stage_chunk(int i0, uint32_t st,
                                            int n0, int o0, int tid) {
    {   // g plane: 512 x 16B
        int ir = tid >> 4, o4 = (tid & 15) * 4;
        cp16(st + SG_OFF + (uint32_t)(ir * OT + o4) * 4,
             &gG[(i0 + ir) * DIM + o0 + o4]);
    }
    #pragma unroll
    for (int k = tid; k < KC * OT / 2; k += THREADS) {   // 1024 each
        int ir = k >> 5, o2 = (k & 31) * 2;
        cp16(st + SWYZ_OFF + (uint32_t)(ir * OT + o2) * 8,
             &gWyz[(i0 + ir) * DIM + o0 + o2]);
        cp16(st + SPQ_OFF + (uint32_t)(ir * OT + o2) * 8,
             &gPQ[(i0 + ir) * DIM + o0 + o2]);
    }
    #pragma unroll
    for (int k = tid; k < KC * NT / 2; k += THREADS) {   // 2048 x 16B
        int ir = k >> 6, n2 = (k & 63) * 2;
        cp16(st + SROW_OFF + (uint32_t)(ir * NT + n2) * 8,
             &gRowT[(i0 + ir) * N_ROWS + n0 + n2]);
    }
}

__global__ __launch_bounds__(THREADS, 1)
void NPU_main_kernel(float* __restrict__ out) {
    extern __shared__ char smem[];
    const uint32_t sbase = (uint32_t)__cvta_generic_to_shared(smem);

    const int tid = threadIdx.x;
    const int n0  = blockIdx.x * NT;
    const int o0  = blockIdx.y * OT;
    const int to  = (tid & 15) * OR;   // col offset in tile
    const int tn  = (tid >> 4) * NR;   // row offset in tile

    unsigned long long AB[NR][OR];
    #pragma unroll
    for (int r = 0; r < NR; r++)
        #pragma unroll
        for (int j = 0; j < OR; j++) AB[r][j] = 0ULL;

    // prologue: stage chunk 0 into stage 0
    stage_chunk(0, sbase, n0, o0, tid);
    asm volatile("cp.async.commit_group;");

    for (int c = 0; c < NCH; c++) {
        const int s = c & 1;
        if (c + 1 < NCH) {
            stage_chunk((c + 1) * KC, sbase + (uint32_t)((s ^ 1) * STG_BYTES),
                        n0, o0, tid);
            asm volatile("cp.async.commit_group;");
            asm volatile("cp.async.wait_group 1;");
        } else {
            asm volatile("cp.async.wait_group 0;");
        }
        __syncthreads();   // chunk c data visible to all

        const char* stg  = smem + s * STG_BYTES;
        const float*  sG   = (const float*) (stg + SG_OFF);
        const float2* sWyz = (const float2*)(stg + SWYZ_OFF);
        const float2* sPQ  = (const float2*)(stg + SPQ_OFF);
        const float2* sRow = (const float2*)(stg + SROW_OFF);

        // ---- hot loop (R3 codegen: scalar lg2, FFMA2 accumulate) ----
        #pragma unroll 2
        for (int i = 0; i < KC; i++) {
            float4 gv = *(const float4*)&sG[i * OT + to];
            ulonglong2 w01 = *(const ulonglong2*)&sWyz[i * OT + to];
            ulonglong2 w23 = *(const ulonglong2*)&sWyz[i * OT + to + 2];
            ulonglong2 p01 = *(const ulonglong2*)&sPQ [i * OT + to];
            ulonglong2 p23 = *(const ulonglong2*)&sPQ [i * OT + to + 2];
            unsigned long long wj[OR] = {w01.x, w01.y, w23.x, w23.y};
            unsigned long long pj[OR] = {p01.x, p01.y, p23.x, p23.y};
            float gj[OR] = {gv.x, gv.y, gv.z, gv.w};

            float2 rv[NR];
            unsigned long long nfnf[NR];
            #pragma unroll
            for (int r = 0; r < NR; r++) {
                rv[r] = sRow[i * NT + tn + r];
                PACK_DUP(nfnf[r], __float_as_uint(rv[r].y));
            }

            #pragma unroll
            for (int r = 0; r < NR; r++) {
                #pragma unroll
                for (int j = 0; j < OR; j++) {
                    float R = fmaf(rv[r].x, gj[j], 1.0f);  // a*g + (1-g)
                    float t = __log2f(R);                   // MUFU.LG2
                    unsigned long long tt;
                    PACK_DUP(tt, __float_as_uint(t));
                    FMA_F32X2(AB[r][j], tt, wj[j]);         // (A,B) += t*(wy,wz)
                    FMA_F32X2(AB[r][j], nfnf[r], pj[j]);    // (A,B) += nf*(P,Q)
                }
            }
        }
        __syncthreads();   // stage s free for restaging
    }

    // ---- epilogue: out = exp(A) * cos(B) ----
    #pragma unroll
    for (int r = 0; r < NR; r++) {
        float4 v;
        float av[OR], bv[OR];
        #pragma unroll
        for (int j = 0; j < OR; j++) {
            av[j] = __uint_as_float((unsigned int)(AB[r][j] & 0xffffffffULL));
            bv[j] = __uint_as_float((unsigned int)(AB[r][j] >> 32));
        }
        v.x = expf(av[0]) * cosf(bv[0]);
        v.y = expf(av[1]) * cosf(bv[1]);
        v.z = expf(av[2]) * cosf(bv[2]);
        v.w = expf(av[3]) * cosf(bv[3]);
        *(float4*)&out[(n0 + tn + r) * DIM + o0 + to] = v;
    }
}

extern "C" void kernel_launch(void* const* d_in, const int* in_sizes, int n_in,
                              void* d_out, int out_size) {
    const float* x  = (const float*)d_in[0];
    const float* Wr = (const float*)d_in[1];
    const float* Wi = (const float*)d_in[2];
    const float* G  = (const float*)d_in[3];
    float* out = (float*)d_out;
    (void)in_sizes; (void)n_in; (void)out_size;

    NPU_prep_kernel<<<(DIM * DIM + 255) / 256, 256>>>(Wr, Wi, G);
    NPU_xform_kernel<<<dim3(N_ROWS / 32, DIM / 32), 256>>>(x);

    cudaFuncSetAttribute(NPU_main_kernel,
                         cudaFuncAttributeMaxDynamicSharedMemorySize, SMEM_TOTAL);
    dim3 grid(N_ROWS / NT, DIM / OT);
    NPU_main_kernel<<<grid, THREADS, SMEM_TOTAL>>>(out);
}

// round 9
// speedup vs baseline: 1.6440x; 1.0332x over previous
#include <cuda_runtime.h>
#include <math.h>
#include <stdint.h>

#define N_ROWS 8192
#define DIM    128

#define NT 128           // rows per block
#define OT 64            // cols per block
#define KC 32            // i-chunk staged in smem
#define NCH (DIM / KC)   // 4 chunks
#define THREADS 512
#define NR 4             // rows per thread
#define OR 4             // cols per thread
#define XSTR 36          // padded float stride for x rows (144B, 16B-aligned)

// ---- packed weights (prep kernel output) ----
__device__ float  gG  [DIM * DIM];
__device__ float2 gWyz[DIM * DIM];   // (ln2*Wr, ln2*Wi)
__device__ float2 gPQ [DIM * DIM];   // (-pi*g*Wi, pi*g*Wr)

__global__ void NPU_prep_kernel(const float* __restrict__ Wr,
                                const float* __restrict__ Wi,
                                const float* __restrict__ G) {
    int idx = blockIdx.x * blockDim.x + threadIdx.x;
    if (idx >= DIM * DIM) return;
    float g = fminf(fmaxf(G[idx], 0.0f), 1.0f);
    float wr = Wr[idx];
    float wi = Wi[idx];
    const float LN2 = 0.69314718055994530942f;
    const float PI  = 3.14159265358979323846f;
    gG[idx]   = g;
    gWyz[idx] = make_float2(LN2 * wr, LN2 * wi);
    gPQ[idx]  = make_float2(-PI * g * wi, PI * g * wr);
}

// ---- smem: two stages, each g + wyz + pq + raw x rows ----
#define SG_OFF    0
#define SWYZ_OFF  (KC * OT * 4)                    //  8192
#define SPQ_OFF   (SWYZ_OFF + KC * OT * 8)         // 24576
#define SROW_OFF  (SPQ_OFF + KC * OT * 8)          // 40960
#define STG_BYTES (SROW_OFF + NT * XSTR * 4)       // 40960 + 18432 = 59392
#define SMEM_TOTAL (2 * STG_BYTES)                 // 118784

#define FMA_F32X2(d, a, b) \
    asm("fma.rn.f32x2 %0, %1, %2, %0;" : "+l"(d) : "l"(a), "l"(b))
#define PACK_DUP(d, s) \
    asm("mov.b64 %0, {%1, %1};" : "=l"(d) : "r"(s))

__device__ __forceinline__ void cp16(uint32_t dst, const void* src) {
    asm volatile("cp.async.cg.shared.global [%0], [%1], 16;"
                 :: "r"(dst), "l"(src));
}

__device__ __forceinline__ void stage_chunk(const float* __restrict__ x,
                                            int i0, uint32_t st,
                                            int n0, int o0, int tid) {
    {   // g plane: 512 x 16B (1 per thread)
        int ir = tid >> 4, o4 = (tid & 15) * 4;
        cp16(st + SG_OFF + (uint32_t)(ir * OT + o4) * 4,
             &gG[(i0 + ir) * DIM + o0 + o4]);
    }
    #pragma unroll
    for (int k = tid; k < KC * OT / 2; k += THREADS) {   // 1024 each (2/thread)
        int ir = k >> 5, o2 = (k & 31) * 2;
        cp16(st + SWYZ_OFF + (uint32_t)(ir * OT + o2) * 8,
             &gWyz[(i0 + ir) * DIM + o0 + o2]);
        cp16(st + SPQ_OFF + (uint32_t)(ir * OT + o2) * 8,
             &gPQ[(i0 + ir) * DIM + o0 + o2]);
    }
    #pragma unroll
    for (int k = tid; k < NT * KC / 4; k += THREADS) {   // 1024 x 16B (2/thread)
        int n  = k >> 3;              // 0..127
        int s4 = (k & 7) * 4;         // float offset within the 32-float row chunk
        cp16(st + SROW_OFF + (uint32_t)(n * XSTR + s4) * 4,
             &x[(n0 + n) * DIM + i0 + s4]);
    }
}

__global__ __launch_bounds__(THREADS, 1)
void NPU_main_kernel(const float* __restrict__ x, float* __restrict__ out) {
    extern __shared__ char smem[];
    const uint32_t sbase = (uint32_t)__cvta_generic_to_shared(smem);

    const int tid = threadIdx.x;
    const int n0  = blockIdx.x * NT;
    const int o0  = blockIdx.y * OT;
    const int to  = (tid & 15) * OR;   // col offset in tile
    const int tn  = (tid >> 4) * NR;   // row offset in tile

    unsigned long long AB[NR][OR];
    #pragma unroll
    for (int r = 0; r < NR; r++)
        #pragma unroll
        for (int j = 0; j < OR; j++) AB[r][j] = 0ULL;

    // prologue: stage chunk 0 into stage 0
    stage_chunk(x, 0, sbase, n0, o0, tid);
    asm volatile("cp.async.commit_group;");

    for (int c = 0; c < NCH; c++) {
        const int s = c & 1;
        if (c + 1 < NCH) {
            stage_chunk(x, (c + 1) * KC, sbase + (uint32_t)((s ^ 1) * STG_BYTES),
                        n0, o0, tid);
            asm volatile("cp.async.commit_group;");
            asm volatile("cp.async.wait_group 1;");
        } else {
            asm volatile("cp.async.wait_group 0;");
        }
        __syncthreads();   // chunk c data visible to all

        const char* stg  = smem + s * STG_BYTES;
        const float*  sG   = (const float*) (stg + SG_OFF);
        const float2* sWyz = (const float2*)(stg + SWYZ_OFF);
        const float2* sPQ  = (const float2*)(stg + SPQ_OFF);
        const float*  sX   = (const float*) (stg + SROW_OFF);

        // ---- hot loop (scalar lg2, FFMA2 accumulate; transform inline) ----
        #pragma unroll 2
        for (int i = 0; i < KC; i++) {
            float4 gv = *(const float4*)&sG[i * OT + to];
            ulonglong2 w01 = *(const ulonglong2*)&sWyz[i * OT + to];
            ulonglong2 w23 = *(const ulonglong2*)&sWyz[i * OT + to + 2];
            ulonglong2 p01 = *(const ulonglong2*)&sPQ [i * OT + to];
            ulonglong2 p23 = *(const ulonglong2*)&sPQ [i * OT + to + 2];
            unsigned long long wj[OR] = {w01.x, w01.y, w23.x, w23.y};
            unsigned long long pj[OR] = {p01.x, p01.y, p23.x, p23.y};
            float gj[OR] = {gv.x, gv.y, gv.z, gv.w};

            float am1[NR];
            unsigned long long nfnf[NR];
            #pragma unroll
            for (int r = 0; r < NR; r++) {
                float xr = sX[(tn + r) * XSTR + i];
                am1[r] = (fabsf(xr) + 1e-36f) - 1.0f;
                float nf = xr < 0.0f ? 1.0f : 0.0f;
                PACK_DUP(nfnf[r], __float_as_uint(nf));
            }

            #pragma unroll
            for (int r = 0; r < NR; r++) {
                #pragma unroll
                for (int j = 0; j < OR; j++) {
                    float R = fmaf(am1[r], gj[j], 1.0f);   // a*g + (1-g)
                    float t = __log2f(R);                   // MUFU.LG2
                    unsigned long long tt;
                    PACK_DUP(tt, __float_as_uint(t));
                    FMA_F32X2(AB[r][j], tt, wj[j]);         // (A,B) += t*(wy,wz)
                    FMA_F32X2(AB[r][j], nfnf[r], pj[j]);    // (A,B) += nf*(P,Q)
                }
            }
        }
        __syncthreads();   // stage s free for restaging
    }

    // ---- epilogue: out = exp(A) * cos(B) (fast MUFU paths; 1M outputs) ----
    #pragma unroll
    for (int r = 0; r < NR; r++) {
        float4 v;
        float av[OR], bv[OR];
        #pragma unroll
        for (int j = 0; j < OR; j++) {
            av[j] = __uint_as_float((unsigned int)(AB[r][j] & 0xffffffffULL));
            bv[j] = __uint_as_float((unsigned int)(AB[r][j] >> 32));
        }
        v.x = __expf(av[0]) * __cosf(bv[0]);
        v.y = __expf(av[1]) * __cosf(bv[1]);
        v.z = __expf(av[2]) * __cosf(bv[2]);
        v.w = __expf(av[3]) * __cosf(bv[3]);
        *(float4*)&out[(n0 + tn + r) * DIM + o0 + to] = v;
    }
}

extern "C" void kernel_launch(void* const* d_in, const int* in_sizes, int n_in,
                              void* d_out, int out_size) {
    const float* x  = (const float*)d_in[0];
    const float* Wr = (const float*)d_in[1];
    const float* Wi = (const float*)d_in[2];
    const float* G  = (const float*)d_in[3];
    float* out = (float*)d_out;
    (void)in_sizes; (void)n_in; (void)out_size;

    NPU_prep_kernel<<<(DIM * DIM + 255) / 256, 256>>>(Wr, Wi, G);

    cudaFuncSetAttribute(NPU_main_kernel,
                         cudaFuncAttributeMaxDynamicSharedMemorySize, SMEM_TOTAL);
    dim3 grid(N_ROWS / NT, DIM / OT);
    NPU_main_kernel<<<grid, THREADS, SMEM_TOTAL>>>(x, out);
}

// round 11
// speedup vs baseline: 1.7903x; 1.0890x over previous
#include <cuda_runtime.h>
#include <math.h>
#include <stdint.h>

#define N_ROWS 8192
#define DIM    128

#define NT 56            // rows per block -> 147 blocks (one per SM, near-full chip)
#define KC 32            // i-chunk staged in smem
#define NCH (DIM / KC)   // 4 chunks
#define THREADS 512      // 32 col-threads x 16 warps
#define OR 4             // cols per thread (32*4 = 128 = full o)
#define XSTR 36          // padded float stride for x rows
#define NBLOCKS ((N_ROWS + NT - 1) / NT)   // 147

// ---- packed weights (prep kernel output) ----
__device__ float  gG  [DIM * DIM];
__device__ float2 gWyz[DIM * DIM];   // (ln2*Wr, ln2*Wi)
__device__ float2 gPQ [DIM * DIM];   // (-pi*g*Wi, pi*g*Wr)

__global__ void NPU_prep_kernel(const float* __restrict__ Wr,
                                const float* __restrict__ Wi,
                                const float* __restrict__ G) {
    int idx = blockIdx.x * blockDim.x + threadIdx.x;
    if (idx >= DIM * DIM) return;
    float g = fminf(fmaxf(G[idx], 0.0f), 1.0f);
    float wr = Wr[idx];
    float wi = Wi[idx];
    const float LN2 = 0.69314718055994530942f;
    const float PI  = 3.14159265358979323846f;
    gG[idx]   = g;
    gWyz[idx] = make_float2(LN2 * wr, LN2 * wi);
    gPQ[idx]  = make_float2(-PI * g * wi, PI * g * wr);
}

// ---- smem: two stages, each g + wyz + pq + raw x rows (full 128-col weights) ----
#define SG_OFF    0
#define SWYZ_OFF  (KC * DIM * 4)                   // 16384
#define SPQ_OFF   (SWYZ_OFF + KC * DIM * 8)        // 49152
#define SX_OFF    (SPQ_OFF + KC * DIM * 8)         // 81920
#define STG_BYTES (((SX_OFF + NT * XSTR * 4) + 127) & ~127)   // 90112
#define SMEM_TOTAL (2 * STG_BYTES)                 // 180224

#define FMA_F32X2(d, a, b) \
    asm("fma.rn.f32x2 %0, %1, %2, %0;" : "+l"(d) : "l"(a), "l"(b))
#define PACK_DUP(d, s) \
    asm("mov.b64 %0, {%1, %1};" : "=l"(d) : "r"(s))

__device__ __forceinline__ void cp16(uint32_t dst, const void* src) {
    asm volatile("cp.async.cg.shared.global [%0], [%1], 16;"
                 :: "r"(dst), "l"(src));
}

__device__ __forceinline__ void stage_chunk(const float* __restrict__ x,
                                            int i0, uint32_t st,
                                            int n0, int tid) {
    #pragma unroll
    for (int k = tid; k < KC * DIM / 4; k += THREADS) {   // g: 1024 cp16
        int ir = k >> 5, o4 = (k & 31) * 4;
        cp16(st + SG_OFF + (uint32_t)(ir * DIM + o4) * 4,
             &gG[(i0 + ir) * DIM + o4]);
    }
    #pragma unroll
    for (int k = tid; k < KC * DIM / 2; k += THREADS) {   // wyz,pq: 2048 each
        int ir = k >> 6, o2 = (k & 63) * 2;
        cp16(st + SWYZ_OFF + (uint32_t)(ir * DIM + o2) * 8,
             &gWyz[(i0 + ir) * DIM + o2]);
        cp16(st + SPQ_OFF + (uint32_t)(ir * DIM + o2) * 8,
             &gPQ[(i0 + ir) * DIM + o2]);
    }
    if (tid < NT * KC / 4) {                              // x: 448 cp16
        int n  = tid >> 3;            // 0..55
        int s4 = (tid & 7) * 4;       // 0..28
        int ng = n0 + n;
        if (ng >= N_ROWS) ng = N_ROWS - 1;   // clamp (valid floats, stores guarded)
        cp16(st + SX_OFF + (uint32_t)(n * XSTR + s4) * 4,
             &x[ng * DIM + i0 + s4]);
    }
}

// Hot loop over one KC-chunk for NRA rows (warp-uniform specialization).
template<int NRA>
__device__ __forceinline__ void hot_chunk(const float* __restrict__ sG,
                                          const float2* __restrict__ sWyz,
                                          const float2* __restrict__ sPQ,
                                          const float* __restrict__ sX,
                                          int oc, int w,
                                          unsigned long long (&AB)[4][OR]) {
    #pragma unroll 2
    for (int i = 0; i < KC; i++) {
        float4 gv = *(const float4*)&sG[i * DIM + oc];
        ulonglong2 w01 = *(const ulonglong2*)&sWyz[i * DIM + oc];
        ulonglong2 w23 = *(const ulonglong2*)&sWyz[i * DIM + oc + 2];
        ulonglong2 p01 = *(const ulonglong2*)&sPQ [i * DIM + oc];
        ulonglong2 p23 = *(const ulonglong2*)&sPQ [i * DIM + oc + 2];
        unsigned long long wj[OR] = {w01.x, w01.y, w23.x, w23.y};
        unsigned long long pj[OR] = {p01.x, p01.y, p23.x, p23.y};
        float gj[OR] = {gv.x, gv.y, gv.z, gv.w};

        float am1[NRA];
        unsigned long long nfnf[NRA];
        #pragma unroll
        for (int r = 0; r < NRA; r++) {
            float xr = sX[(w + 16 * r) * XSTR + i];      // warp-broadcast
            am1[r] = (fabsf(xr) + 1e-36f) - 1.0f;
            float nf = xr < 0.0f ? 1.0f : 0.0f;
            PACK_DUP(nfnf[r], __float_as_uint(nf));
        }

        #pragma unroll
        for (int r = 0; r < NRA; r++) {
            #pragma unroll
            for (int j = 0; j < OR; j++) {
                float R = fmaf(am1[r], gj[j], 1.0f);     // a*g + (1-g)
                float t = __log2f(R);                     // MUFU.LG2
                unsigned long long tt;
                PACK_DUP(tt, __float_as_uint(t));
                FMA_F32X2(AB[r][j], tt, wj[j]);           // (A,B) += t*(wy,wz)
                FMA_F32X2(AB[r][j], nfnf[r], pj[j]);      // (A,B) += nf*(P,Q)
            }
        }
    }
}

__global__ __launch_bounds__(THREADS, 1)
void NPU_main_kernel(const float* __restrict__ x, float* __restrict__ out) {
    extern __shared__ char smem[];
    const uint32_t sbase = (uint32_t)__cvta_generic_to_shared(smem);

    const int tid = threadIdx.x;
    const int n0  = blockIdx.x * NT;
    const int oc  = (tid & 31) * OR;     // col offset (0..124)
    const int w   = tid >> 5;            // warp id = row-thread (0..15)
    const bool four_rows = (w < 8);      // warps 0-7: rows w+16r, r<4; else r<3

    unsigned long long AB[4][OR];
    #pragma unroll
    for (int r = 0; r < 4; r++)
        #pragma unroll
        for (int j = 0; j < OR; j++) AB[r][j] = 0ULL;

    stage_chunk(x, 0, sbase, n0, tid);
    asm volatile("cp.async.commit_group;");

    for (int c = 0; c < NCH; c++) {
        const int s = c & 1;
        if (c + 1 < NCH) {
            stage_chunk(x, (c + 1) * KC, sbase + (uint32_t)((s ^ 1) * STG_BYTES),
                        n0, tid);
            asm volatile("cp.async.commit_group;");
            asm volatile("cp.async.wait_group 1;");
        } else {
            asm volatile("cp.async.wait_group 0;");
        }
        __syncthreads();

        const char* stg = smem + s * STG_BYTES;
        const float*  sG   = (const float*) (stg + SG_OFF);
        const float2* sWyz = (const float2*)(stg + SWYZ_OFF);
        const float2* sPQ  = (const float2*)(stg + SPQ_OFF);
        const float*  sX   = (const float*) (stg + SX_OFF);

        if (four_rows) hot_chunk<4>(sG, sWyz, sPQ, sX, oc, w, AB);
        else           hot_chunk<3>(sG, sWyz, sPQ, sX, oc, w, AB);

        __syncthreads();
    }

    // ---- epilogue: out = exp(A) * cos(B) (fast MUFU paths) ----
    const int nra = four_rows ? 4 : 3;
    #pragma unroll
    for (int r = 0; r < 4; r++) {
        if (r >= nra) break;
        int ng = n0 + w + 16 * r;
        if (ng >= N_ROWS) continue;
        float4 v;
        float av[OR], bv[OR];
        #pragma unroll
        for (int j = 0; j < OR; j++) {
            av[j] = __uint_as_float((unsigned int)(AB[r][j] & 0xffffffffULL));
            bv[j] = __uint_as_float((unsigned int)(AB[r][j] >> 32));
        }
        v.x = __expf(av[0]) * __cosf(bv[0]);
        v.y = __expf(av[1]) * __cosf(bv[1]);
        v.z = __expf(av[2]) * __cosf(bv[2]);
        v.w = __expf(av[3]) * __cosf(bv[3]);
        *(float4*)&out[ng * DIM + oc] = v;
    }
}

extern "C" void kernel_launch(void* const* d_in, const int* in_sizes, int n_in,
                              void* d_out, int out_size) {
    const float* x  = (const float*)d_in[0];
    const float* Wr = (const float*)d_in[1];
    const float* Wi = (const float*)d_in[2];
    const float* G  = (const float*)d_in[3];
    float* out = (float*)d_out;
    (void)in_sizes; (void)n_in; (void)out_size;

    NPU_prep_kernel<<<(DIM * DIM + 255) / 256, 256>>>(Wr, Wi, G);

    cudaFuncSetAttribute(NPU_main_kernel,
                         cudaFuncAttributeMaxDynamicSharedMemorySize, SMEM_TOTAL);
    NPU_main_kernel<<<NBLOCKS, THREADS, SMEM_TOTAL>>>(x, out);
}